// round 1
// baseline (speedup 1.0000x reference)
#include <cuda_runtime.h>

#define NQ    20000
#define NA    100000
#define KNN   32
#define HID   128
#define E_F   16
#define HEADS 8

// ---------------- scratch (static device globals; no runtime alloc) -------------
__device__ __align__(16) float g_Qq [NQ * HID];
__device__ __align__(16) float g_Ka [NA * HID];
__device__ __align__(16) float g_Va [NA * HID];
__device__ __align__(16) float g_agg[NQ * HID];
__device__ __align__(16) float g_H1 [NQ * HID];

// ---------------------------------------------------------------------------
// C[M,128] = f(A @ B^T + bias [+ resid]) with optional ReLU / LayerNorm.
// A rows always have stride 128. If A1 != null, logical A = concat(A0, A1)
// along K (K must be 256); B is row-major [128, K] (K-major, matching W @ x^T).
// Tiles: BM=64, BN=128(full), BK=16. 256 threads; 8x4 register micro-tiles.
// ---------------------------------------------------------------------------
__global__ __launch_bounds__(256) void gemm_nt(
    const float* __restrict__ A0, const float* __restrict__ A1,
    const float* __restrict__ B,  const float* __restrict__ bias,
    const float* __restrict__ resid, const float* __restrict__ gamma,
    const float* __restrict__ beta, float* __restrict__ C,
    int M, int K, int relu, int do_ln)
{
    __shared__ __align__(16) float As[16][64];
    __shared__ __align__(16) float Bs[16][128];

    const int tid  = threadIdx.x;
    const int ty   = tid >> 5;      // warp id 0..7  -> rows ty*8 .. ty*8+7
    const int tx   = tid & 31;      // lane          -> cols tx*4 .. tx*4+3
    const int brow = blockIdx.x * 64;

    float acc[8][4];
#pragma unroll
    for (int i = 0; i < 8; i++)
#pragma unroll
        for (int j = 0; j < 4; j++) acc[i][j] = 0.f;

    const int ar = tid >> 2, ak = (tid & 3) * 4;   // A tile load map (1 float4/thr)
    const int br = tid >> 1, bk = (tid & 1) * 8;   // B tile load map (2 float4/thr)

    for (int kb = 0; kb < K; kb += 16) {
        const float* Ap  = (A1 != nullptr && kb >= HID) ? A1 : A0;
        const int   koff = (A1 != nullptr && kb >= HID) ? (kb - HID) : kb;

        float4 av = make_float4(0.f, 0.f, 0.f, 0.f);
        const int arow = brow + ar;
        if (arow < M) av = *(const float4*)&Ap[(size_t)arow * HID + koff + ak];
        const float4 bv0 = *(const float4*)&B[(size_t)br * K + kb + bk];
        const float4 bv1 = *(const float4*)&B[(size_t)br * K + kb + bk + 4];

        __syncthreads();   // previous tile's compute done before overwrite
        As[ak + 0][ar] = av.x;  As[ak + 1][ar] = av.y;
        As[ak + 2][ar] = av.z;  As[ak + 3][ar] = av.w;
        Bs[bk + 0][br] = bv0.x; Bs[bk + 1][br] = bv0.y;
        Bs[bk + 2][br] = bv0.z; Bs[bk + 3][br] = bv0.w;
        Bs[bk + 4][br] = bv1.x; Bs[bk + 5][br] = bv1.y;
        Bs[bk + 6][br] = bv1.z; Bs[bk + 7][br] = bv1.w;
        __syncthreads();

#pragma unroll
        for (int k = 0; k < 16; k++) {
            const float4 a0 = *(const float4*)&As[k][ty * 8];       // broadcast
            const float4 a1 = *(const float4*)&As[k][ty * 8 + 4];   // broadcast
            const float4 b4 = *(const float4*)&Bs[k][tx * 4];       // conflict-free
            const float a[8]  = {a0.x, a0.y, a0.z, a0.w, a1.x, a1.y, a1.z, a1.w};
            const float bb[4] = {b4.x, b4.y, b4.z, b4.w};
#pragma unroll
            for (int i = 0; i < 8; i++)
#pragma unroll
                for (int j = 0; j < 4; j++)
                    acc[i][j] = fmaf(a[i], bb[j], acc[i][j]);
        }
    }

    // ------------------------- epilogue -------------------------
    const int col = tx * 4;
    float4 bi = make_float4(0.f, 0.f, 0.f, 0.f);
    if (bias) bi = *(const float4*)&bias[col];
    float4 ga = make_float4(1.f, 1.f, 1.f, 1.f);
    float4 be = make_float4(0.f, 0.f, 0.f, 0.f);
    if (do_ln) { ga = *(const float4*)&gamma[col]; be = *(const float4*)&beta[col]; }

#pragma unroll
    for (int i = 0; i < 8; i++) {
        const int row = brow + ty * 8 + i;      // uniform across the warp
        if (row >= M) break;
        float4 v = make_float4(acc[i][0] + bi.x, acc[i][1] + bi.y,
                               acc[i][2] + bi.z, acc[i][3] + bi.w);
        if (resid) {
            const float4 r = *(const float4*)&resid[(size_t)row * HID + col];
            v.x += r.x; v.y += r.y; v.z += r.z; v.w += r.w;
        }
        if (relu) {
            v.x = fmaxf(v.x, 0.f); v.y = fmaxf(v.y, 0.f);
            v.z = fmaxf(v.z, 0.f); v.w = fmaxf(v.w, 0.f);
        }
        if (do_ln) {
            float s  = v.x + v.y + v.z + v.w;
            float ss = v.x * v.x + v.y * v.y + v.z * v.z + v.w * v.w;
#pragma unroll
            for (int o = 16; o > 0; o >>= 1) {
                s  += __shfl_xor_sync(0xffffffffu, s,  o);
                ss += __shfl_xor_sync(0xffffffffu, ss, o);
            }
            const float mean = s * (1.f / HID);
            const float var  = ss * (1.f / HID) - mean * mean;
            const float inv  = rsqrtf(var + 1e-5f);
            v.x = (v.x - mean) * inv * ga.x + be.x;
            v.y = (v.y - mean) * inv * ga.y + be.y;
            v.z = (v.z - mean) * inv * ga.z + be.z;
            v.w = (v.w - mean) * inv * ga.w + be.w;
        }
        *(float4*)&C[(size_t)row * HID + col] = v;
    }
}

// ---------------------------------------------------------------------------
// Attention: one warp per query. lane l owns output dims [4l, 4l+4) which lie
// entirely inside head h = l/4 (D_HEAD = 16 = 4 lanes). Head dot-products
// reduce with 2x shfl_xor inside 4-lane groups. KNN=32 scores live in regs.
// ---------------------------------------------------------------------------
__global__ __launch_bounds__(256) void attn_kernel(
    const float* __restrict__ Qq, const float* __restrict__ Ka,
    const float* __restrict__ Va, const float* __restrict__ edge_attr,
    const int*   __restrict__ src_idx, const float* __restrict__ W_rbf,
    float* __restrict__ agg)
{
    const int warp = threadIdx.x >> 5;
    const int lane = threadIdx.x & 31;
    const int q = blockIdx.x * 8 + warp;
    if (q >= NQ) return;

    const int h = lane >> 2;       // head 0..7
    const int s = lane & 3;        // sub-lane within head

    const float4 q4 = *(const float4*)&Qq[(size_t)q * HID + lane * 4];
    const float4 wr = *(const float4*)&W_rbf[h * E_F + s * 4];

    const int* sp = src_idx + (size_t)q * KNN;
    float sc[KNN];
    int   srcs[KNN];

#pragma unroll
    for (int j = 0; j < KNN; j++) {
        const int srcj = sp[j];
        srcs[j] = srcj;
        const float4 k4 = *(const float4*)&Ka[(size_t)srcj * HID + lane * 4];
        float d = q4.x * k4.x + q4.y * k4.y + q4.z * k4.z + q4.w * k4.w;
        const float4 e4 = *(const float4*)&edge_attr[((size_t)q * KNN + j) * E_F + s * 4];
        float r = e4.x * wr.x + e4.y * wr.y + e4.z * wr.z + e4.w * wr.w;
        d += __shfl_xor_sync(0xffffffffu, d, 1);
        d += __shfl_xor_sync(0xffffffffu, d, 2);
        r += __shfl_xor_sync(0xffffffffu, r, 1);
        r += __shfl_xor_sync(0xffffffffu, r, 2);
        sc[j] = d * 0.25f + r;     // /sqrt(D_HEAD=16) + rbf
    }

    float m = sc[0];
#pragma unroll
    for (int j = 1; j < KNN; j++) m = fmaxf(m, sc[j]);
    float sum = 0.f;
#pragma unroll
    for (int j = 0; j < KNN; j++) { sc[j] = expf(sc[j] - m); sum += sc[j]; }
    const float inv = 1.f / (sum + 1e-16f);

    float4 acc = make_float4(0.f, 0.f, 0.f, 0.f);
#pragma unroll
    for (int j = 0; j < KNN; j++) {
        const float a = sc[j] * inv;
        const float4 v4 = *(const float4*)&Va[(size_t)srcs[j] * HID + lane * 4];
        acc.x = fmaf(a, v4.x, acc.x);
        acc.y = fmaf(a, v4.y, acc.y);
        acc.z = fmaf(a, v4.z, acc.z);
        acc.w = fmaf(a, v4.w, acc.w);
    }
    *(float4*)&agg[(size_t)q * HID + lane * 4] = acc;
}

// ---------------------------------------------------------------------------
extern "C" void kernel_launch(void* const* d_in, const int* in_sizes, int n_in,
                              void* d_out, int out_size)
{
    const float* h_atom    = (const float*)d_in[0];
    const float* h_query   = (const float*)d_in[1];
    const float* edge_attr = (const float*)d_in[2];
    const float* W_q       = (const float*)d_in[3];
    const float* W_k       = (const float*)d_in[4];
    const float* W_v       = (const float*)d_in[5];
    const float* W_rbf     = (const float*)d_in[6];
    const float* W1        = (const float*)d_in[7];
    const float* b1        = (const float*)d_in[8];
    const float* W2        = (const float*)d_in[9];
    const float* b2        = (const float*)d_in[10];
    const float* ln_gamma  = (const float*)d_in[11];
    const float* ln_beta   = (const float*)d_in[12];
    const int*   edge_index= (const int*)  d_in[13];   // [2,E]; row0 = src
    float* out = (float*)d_out;

    float *Qq, *Ka, *Va, *agg, *H1;
    cudaGetSymbolAddress((void**)&Qq,  g_Qq);
    cudaGetSymbolAddress((void**)&Ka,  g_Ka);
    cudaGetSymbolAddress((void**)&Va,  g_Va);
    cudaGetSymbolAddress((void**)&agg, g_agg);
    cudaGetSymbolAddress((void**)&H1,  g_H1);

    const int gq = (NQ + 63) / 64;   // 313
    const int ga = (NA + 63) / 64;   // 1563

    // Per-node projections (NOT per-edge): Qq = h_query @ Wq^T, Ka/Va likewise.
    gemm_nt<<<gq, 256>>>(h_query, nullptr, W_q, nullptr, nullptr, nullptr, nullptr,
                         Qq, NQ, HID, 0, 0);
    gemm_nt<<<ga, 256>>>(h_atom, nullptr, W_k, nullptr, nullptr, nullptr, nullptr,
                         Ka, NA, HID, 0, 0);
    gemm_nt<<<ga, 256>>>(h_atom, nullptr, W_v, nullptr, nullptr, nullptr, nullptr,
                         Va, NA, HID, 0, 0);

    // Segment softmax attention + weighted aggregation (dst[e] = e / KNN).
    attn_kernel<<<NQ / 8, 256>>>(Qq, Ka, Va, edge_attr, edge_index, W_rbf, agg);

    // MLP layer 1 over concat([h_query, agg]) with ReLU.
    gemm_nt<<<gq, 256>>>(h_query, agg, W1, b1, nullptr, nullptr, nullptr,
                         H1, NQ, 2 * HID, 1, 0);
    // MLP layer 2 + bias + residual + LayerNorm fused epilogue.
    gemm_nt<<<gq, 256>>>(H1, nullptr, W2, b2, h_query, ln_gamma, ln_beta,
                         out, NQ, HID, 0, 1);
}

// round 2
// speedup vs baseline: 1.4543x; 1.4543x over previous
#include <cuda_runtime.h>

#define NQ    20000
#define NA    100000
#define KNN   32
#define HID   128
#define E_F   16
#define HEADS 8

// ---------------- scratch (static device globals; no runtime alloc) ----------
__device__ __align__(16) float g_Qq [NQ * HID];
__device__ __align__(16) float g_Ka [NA * HID];
__device__ __align__(16) float g_Va [NA * HID];
__device__ __align__(16) float g_agg[NQ * HID];
__device__ __align__(16) float g_H1 [NQ * HID];

// ------------------------- tf32 helpers --------------------------------------
__device__ __forceinline__ float tf32r(float x) {
    unsigned u;
    asm("cvt.rna.tf32.f32 %0, %1;" : "=r"(u) : "f"(x));
    return __uint_as_float(u);
}
__device__ __forceinline__ float4 cvt4(float4 v) {
    return make_float4(tf32r(v.x), tf32r(v.y), tf32r(v.z), tf32r(v.w));
}
__device__ __forceinline__ void mma8(float* d, unsigned a0, unsigned a1,
                                     unsigned a2, unsigned a3,
                                     unsigned b0, unsigned b1) {
    asm volatile(
        "mma.sync.aligned.m16n8k8.row.col.f32.tf32.tf32.f32 "
        "{%0,%1,%2,%3}, {%4,%5,%6,%7}, {%8,%9}, {%0,%1,%2,%3};"
        : "+f"(d[0]), "+f"(d[1]), "+f"(d[2]), "+f"(d[3])
        : "r"(a0), "r"(a1), "r"(a2), "r"(a3), "r"(b0), "r"(b1));
}

// ---------------------------------------------------------------------------
// Tensor-core GEMM: C[M,128] = f(A @ B^T + bias [+resid]) (ReLU / LayerNorm).
// A rows stride 128 (logical concat(A0,A1) along K if A1 != null, K=256).
// B row-major [128, K]. BM=128, BN=128, BK=16, 256 threads (8 warps).
// Warp w owns rows [w*16, w*16+16) x all 128 cols: 16 m16n8k8 tf32 MMAs/k8.
// Double-buffered smem, 1 sync per K-tile.
// ---------------------------------------------------------------------------
__global__ __launch_bounds__(256) void gemm_tc(
    const float* __restrict__ A0, const float* __restrict__ A1,
    const float* __restrict__ B,  const float* __restrict__ bias,
    const float* __restrict__ resid, const float* __restrict__ gamma,
    const float* __restrict__ beta, float* __restrict__ C,
    int M, int K, int relu, int do_ln)
{
    // As[buf][row][20]  (16 cols used, pad->20 for conflict-free frag LDS)
    // Bf[buf][(n*12 + ks*4 + tig)*2] : float2 pairs (B[n][k8+tig], B[n][k8+tig+4])
    __shared__ float As[2][128 * 20];
    __shared__ float Bf[2][128 * 24];

    const int tid  = threadIdx.x;
    const int warp = tid >> 5;
    const int lane = tid & 31;
    const int g    = lane >> 2;       // 0..7
    const int tig  = lane & 3;        // 0..3
    const int lr   = tid >> 1;        // 0..127 (load row)
    const int lc   = (tid & 1) * 8;   // 0 or 8 (load col base)
    const int brow = blockIdx.x * 128;

    float d[16][4];
#pragma unroll
    for (int i = 0; i < 16; i++)
#pragma unroll
        for (int j = 0; j < 4; j++) d[i][j] = 0.f;

    float4 sa0, sa1, sb0, sb1;

    auto loadg = [&](int kb) {
        const float* Ap = (A1 != nullptr && kb >= HID) ? A1 : A0;
        const int    ko = (A1 != nullptr && kb >= HID) ? (kb - HID) : kb;
        const int r = brow + lr;
        sa0 = make_float4(0.f, 0.f, 0.f, 0.f);
        sa1 = sa0;
        if (r < M) {
            sa0 = *(const float4*)&Ap[(size_t)r * HID + ko + lc];
            sa1 = *(const float4*)&Ap[(size_t)r * HID + ko + lc + 4];
        }
        sb0 = *(const float4*)&B[(size_t)lr * K + kb + lc];
        sb1 = *(const float4*)&B[(size_t)lr * K + kb + lc + 4];
    };

    auto stores = [&](int buf) {
        float* as = &As[buf][lr * 20 + lc];
        *(float4*)as       = cvt4(sa0);
        *(float4*)(as + 4) = cvt4(sa1);
        const int ks = lc >> 3;
        float* bs = &Bf[buf][(lr * 12 + ks * 4) * 2];
        *(float4*)bs       = make_float4(tf32r(sb0.x), tf32r(sb1.x),
                                         tf32r(sb0.y), tf32r(sb1.y));
        *(float4*)(bs + 4) = make_float4(tf32r(sb0.z), tf32r(sb1.z),
                                         tf32r(sb0.w), tf32r(sb1.w));
    };

    auto compute = [&](int buf) {
        const float* ab = &As[buf][(warp * 16 + g) * 20 + tig];
#pragma unroll
        for (int ks = 0; ks < 2; ks++) {
            const unsigned a0 = __float_as_uint(ab[ks * 8 + 0]);
            const unsigned a2 = __float_as_uint(ab[ks * 8 + 4]);
            const unsigned a1 = __float_as_uint(ab[ks * 8 + 8 * 20]);
            const unsigned a3 = __float_as_uint(ab[ks * 8 + 8 * 20 + 4]);
#pragma unroll
            for (int nt = 0; nt < 16; nt++) {
                const float2 bp = *(const float2*)
                    &Bf[buf][((nt * 8 + g) * 12 + ks * 4 + tig) * 2];
                mma8(d[nt], a0, a1, a2, a3,
                     __float_as_uint(bp.x), __float_as_uint(bp.y));
            }
        }
    };

    const int T = K / 16;
    loadg(0);
    stores(0);
    __syncthreads();
    for (int t = 0; t < T; t++) {
        if (t + 1 < T) loadg((t + 1) * 16);
        compute(t & 1);
        if (t + 1 < T) { stores((t + 1) & 1); __syncthreads(); }
    }

    // ------------------------------ epilogue ------------------------------
    const int colb = 2 * tig;
#pragma unroll
    for (int half = 0; half < 2; half++) {
        const int  row = brow + warp * 16 + g + half * 8;
        const bool ok  = row < M;
        float s = 0.f, ss = 0.f;
#pragma unroll
        for (int nt = 0; nt < 16; nt++) {
            const int col = nt * 8 + colb;
            float x0 = d[nt][half * 2 + 0];
            float x1 = d[nt][half * 2 + 1];
            if (bias) {
                const float2 bi = *(const float2*)&bias[col];
                x0 += bi.x; x1 += bi.y;
            }
            if (resid && ok) {
                const float2 rr = *(const float2*)&resid[(size_t)row * HID + col];
                x0 += rr.x; x1 += rr.y;
            }
            if (relu) { x0 = fmaxf(x0, 0.f); x1 = fmaxf(x1, 0.f); }
            d[nt][half * 2 + 0] = x0;
            d[nt][half * 2 + 1] = x1;
            s  += x0 + x1;
            ss += x0 * x0 + x1 * x1;
        }
        if (do_ln) {
            s  += __shfl_xor_sync(0xffffffffu, s, 1);
            s  += __shfl_xor_sync(0xffffffffu, s, 2);
            ss += __shfl_xor_sync(0xffffffffu, ss, 1);
            ss += __shfl_xor_sync(0xffffffffu, ss, 2);
            const float mean = s * (1.f / 128.f);
            const float inv  = rsqrtf(ss * (1.f / 128.f) - mean * mean + 1e-5f);
#pragma unroll
            for (int nt = 0; nt < 16; nt++) {
                const int col = nt * 8 + colb;
                const float2 gg = *(const float2*)&gamma[col];
                const float2 bb = *(const float2*)&beta[col];
                float2 o;
                o.x = (d[nt][half * 2 + 0] - mean) * inv * gg.x + bb.x;
                o.y = (d[nt][half * 2 + 1] - mean) * inv * gg.y + bb.y;
                if (ok) *(float2*)&C[(size_t)row * HID + col] = o;
            }
        } else if (ok) {
#pragma unroll
            for (int nt = 0; nt < 16; nt++) {
                const int col = nt * 8 + colb;
                *(float2*)&C[(size_t)row * HID + col] =
                    make_float2(d[nt][half * 2 + 0], d[nt][half * 2 + 1]);
            }
        }
    }
}

// ---------------------------------------------------------------------------
// Attention: one warp per query; lane l owns out dims [4l,4l+4) of head l/4.
// Scores/alphas and src indices live in SMEM (low reg count -> high occ).
// ---------------------------------------------------------------------------
__global__ __launch_bounds__(256) void attn_kernel(
    const float* __restrict__ Qq, const float* __restrict__ Ka,
    const float* __restrict__ Va, const float* __restrict__ edge_attr,
    const int*   __restrict__ src_idx, const float* __restrict__ W_rbf,
    float* __restrict__ agg)
{
    __shared__ float s_sc[8][8 * 36];   // [warp][head * 36 + j], pad 36
    __shared__ int   s_src[8][32];

    const int warp = threadIdx.x >> 5;
    const int lane = threadIdx.x & 31;
    const int q = blockIdx.x * 8 + warp;
    const int h   = lane >> 2;
    const int sm4 = lane & 3;

    const float4 q4 = *(const float4*)&Qq[(size_t)q * HID + lane * 4];
    const float4 wr = *(const float4*)&W_rbf[h * E_F + sm4 * 4];

    s_src[warp][lane] = src_idx[(size_t)q * KNN + lane];
    __syncwarp();

    // scores
#pragma unroll
    for (int j = 0; j < KNN; j++) {
        const int sj = s_src[warp][j];
        const float4 k4 = *(const float4*)&Ka[(size_t)sj * HID + lane * 4];
        float dd = q4.x * k4.x + q4.y * k4.y + q4.z * k4.z + q4.w * k4.w;
        const float4 e4 = *(const float4*)
            &edge_attr[((size_t)q * KNN + j) * E_F + sm4 * 4];
        const float rr = e4.x * wr.x + e4.y * wr.y + e4.z * wr.z + e4.w * wr.w;
        float t = dd * 0.25f + rr;                 // /sqrt(16) + rbf partial
        t += __shfl_xor_sync(0xffffffffu, t, 1);
        t += __shfl_xor_sync(0xffffffffu, t, 2);
        if (sm4 == 0) s_sc[warp][h * 36 + j] = t;
    }
    __syncwarp();

    // softmax (parallel over lanes: lane handles 8 of the 32 edges of head h)
    float v[8];
    float m = -1e30f;
#pragma unroll
    for (int t = 0; t < 8; t++) {
        v[t] = s_sc[warp][h * 36 + sm4 + 4 * t];
        m = fmaxf(m, v[t]);
    }
    m = fmaxf(m, __shfl_xor_sync(0xffffffffu, m, 1));
    m = fmaxf(m, __shfl_xor_sync(0xffffffffu, m, 2));
    float sum = 0.f;
#pragma unroll
    for (int t = 0; t < 8; t++) { v[t] = __expf(v[t] - m); sum += v[t]; }
    sum += __shfl_xor_sync(0xffffffffu, sum, 1);
    sum += __shfl_xor_sync(0xffffffffu, sum, 2);
    const float inv = 1.f / (sum + 1e-16f);
#pragma unroll
    for (int t = 0; t < 8; t++) s_sc[warp][h * 36 + sm4 + 4 * t] = v[t] * inv;
    __syncwarp();

    // weighted V aggregation
    float4 acc = make_float4(0.f, 0.f, 0.f, 0.f);
#pragma unroll
    for (int j = 0; j < KNN; j++) {
        const float a  = s_sc[warp][h * 36 + j];
        const int   sj = s_src[warp][j];
        const float4 v4 = *(const float4*)&Va[(size_t)sj * HID + lane * 4];
        acc.x = fmaf(a, v4.x, acc.x);
        acc.y = fmaf(a, v4.y, acc.y);
        acc.z = fmaf(a, v4.z, acc.z);
        acc.w = fmaf(a, v4.w, acc.w);
    }
    *(float4*)&agg[(size_t)q * HID + lane * 4] = acc;
}

// ---------------------------------------------------------------------------
extern "C" void kernel_launch(void* const* d_in, const int* in_sizes, int n_in,
                              void* d_out, int out_size)
{
    const float* h_atom    = (const float*)d_in[0];
    const float* h_query   = (const float*)d_in[1];
    const float* edge_attr = (const float*)d_in[2];
    const float* W_q       = (const float*)d_in[3];
    const float* W_k       = (const float*)d_in[4];
    const float* W_v       = (const float*)d_in[5];
    const float* W_rbf     = (const float*)d_in[6];
    const float* W1        = (const float*)d_in[7];
    const float* b1        = (const float*)d_in[8];
    const float* W2        = (const float*)d_in[9];
    const float* b2        = (const float*)d_in[10];
    const float* ln_gamma  = (const float*)d_in[11];
    const float* ln_beta   = (const float*)d_in[12];
    const int*   edge_index= (const int*)  d_in[13];   // [2,E]; row0 = src
    float* out = (float*)d_out;

    float *Qq, *Ka, *Va, *agg, *H1;
    cudaGetSymbolAddress((void**)&Qq,  g_Qq);
    cudaGetSymbolAddress((void**)&Ka,  g_Ka);
    cudaGetSymbolAddress((void**)&Va,  g_Va);
    cudaGetSymbolAddress((void**)&agg, g_agg);
    cudaGetSymbolAddress((void**)&H1,  g_H1);

    const int gq = (NQ + 127) / 128;   // 157
    const int ga = (NA + 127) / 128;   // 782

    // per-node projections (tf32 tensor cores)
    gemm_tc<<<gq, 256>>>(h_query, nullptr, W_q, nullptr, nullptr, nullptr, nullptr,
                         Qq, NQ, HID, 0, 0);
    gemm_tc<<<ga, 256>>>(h_atom, nullptr, W_k, nullptr, nullptr, nullptr, nullptr,
                         Ka, NA, HID, 0, 0);
    gemm_tc<<<ga, 256>>>(h_atom, nullptr, W_v, nullptr, nullptr, nullptr, nullptr,
                         Va, NA, HID, 0, 0);

    // segment-softmax attention + aggregation (dst[e] = e / KNN)
    attn_kernel<<<NQ / 8, 256>>>(Qq, Ka, Va, edge_attr, edge_index, W_rbf, agg);

    // MLP1 over concat([h_query, agg]) with ReLU
    gemm_tc<<<gq, 256>>>(h_query, agg, W1, b1, nullptr, nullptr, nullptr,
                         H1, NQ, 2 * HID, 1, 0);
    // MLP2 + bias + residual + LayerNorm fused epilogue
    gemm_tc<<<gq, 256>>>(H1, nullptr, W2, b2, h_query, ln_gamma, ln_beta,
                         out, NQ, HID, 0, 1);
}

// round 3
// speedup vs baseline: 1.5626x; 1.0745x over previous
#include <cuda_runtime.h>
#include <cuda_fp16.h>

#define NQ    20000
#define NA    100000
#define KNN   32
#define HID   128
#define E_F   16
#define HEADS 8

// ---------------- scratch (static device globals; no runtime alloc) ----------
__device__ __align__(16) float  g_Qq [NQ * HID];
__device__ __align__(16) __half g_Ka [NA * HID];
__device__ __align__(16) __half g_Va [NA * HID];
__device__ __align__(16) float  g_agg[NQ * HID];
__device__ __align__(16) float  g_H1 [NQ * HID];

// ------------------------- tf32 helpers --------------------------------------
__device__ __forceinline__ float tf32r(float x) {
    unsigned u;
    asm("cvt.rna.tf32.f32 %0, %1;" : "=r"(u) : "f"(x));
    return __uint_as_float(u);
}
__device__ __forceinline__ float4 cvt4(float4 v) {
    return make_float4(tf32r(v.x), tf32r(v.y), tf32r(v.z), tf32r(v.w));
}
__device__ __forceinline__ void mma8(float* d, unsigned a0, unsigned a1,
                                     unsigned a2, unsigned a3,
                                     unsigned b0, unsigned b1) {
    asm volatile(
        "mma.sync.aligned.m16n8k8.row.col.f32.tf32.tf32.f32 "
        "{%0,%1,%2,%3}, {%4,%5,%6,%7}, {%8,%9}, {%0,%1,%2,%3};"
        : "+f"(d[0]), "+f"(d[1]), "+f"(d[2]), "+f"(d[3])
        : "r"(a0), "r"(a1), "r"(a2), "r"(a3), "r"(b0), "r"(b1));
}

// ---------------------------------------------------------------------------
// Tensor-core GEMM: C[M,128] = f(A @ B^T + bias [+resid]) (ReLU / LayerNorm).
// A rows stride 128 (logical concat(A0,A1) along K if A1 != null, K=256).
// B row-major [128, K]. BM=128, BN=128, BK=16, 256 threads (8 warps).
// ---------------------------------------------------------------------------
__global__ __launch_bounds__(256) void gemm_tc(
    const float* __restrict__ A0, const float* __restrict__ A1,
    const float* __restrict__ B,  const float* __restrict__ bias,
    const float* __restrict__ resid, const float* __restrict__ gamma,
    const float* __restrict__ beta, float* __restrict__ C,
    int M, int K, int relu, int do_ln)
{
    __shared__ float As[2][128 * 20];
    __shared__ float Bf[2][128 * 24];

    const int tid  = threadIdx.x;
    const int warp = tid >> 5;
    const int lane = tid & 31;
    const int g    = lane >> 2;
    const int tig  = lane & 3;
    const int lr   = tid >> 1;
    const int lc   = (tid & 1) * 8;
    const int brow = blockIdx.x * 128;

    float d[16][4];
#pragma unroll
    for (int i = 0; i < 16; i++)
#pragma unroll
        for (int j = 0; j < 4; j++) d[i][j] = 0.f;

    float4 sa0, sa1, sb0, sb1;

    auto loadg = [&](int kb) {
        const float* Ap = (A1 != nullptr && kb >= HID) ? A1 : A0;
        const int    ko = (A1 != nullptr && kb >= HID) ? (kb - HID) : kb;
        const int r = brow + lr;
        sa0 = make_float4(0.f, 0.f, 0.f, 0.f);
        sa1 = sa0;
        if (r < M) {
            sa0 = *(const float4*)&Ap[(size_t)r * HID + ko + lc];
            sa1 = *(const float4*)&Ap[(size_t)r * HID + ko + lc + 4];
        }
        sb0 = *(const float4*)&B[(size_t)lr * K + kb + lc];
        sb1 = *(const float4*)&B[(size_t)lr * K + kb + lc + 4];
    };

    auto stores = [&](int buf) {
        float* as = &As[buf][lr * 20 + lc];
        *(float4*)as       = cvt4(sa0);
        *(float4*)(as + 4) = cvt4(sa1);
        const int ks = lc >> 3;
        float* bs = &Bf[buf][(lr * 12 + ks * 4) * 2];
        *(float4*)bs       = make_float4(tf32r(sb0.x), tf32r(sb1.x),
                                         tf32r(sb0.y), tf32r(sb1.y));
        *(float4*)(bs + 4) = make_float4(tf32r(sb0.z), tf32r(sb1.z),
                                         tf32r(sb0.w), tf32r(sb1.w));
    };

    auto compute = [&](int buf) {
        const float* ab = &As[buf][(warp * 16 + g) * 20 + tig];
#pragma unroll
        for (int ks = 0; ks < 2; ks++) {
            const unsigned a0 = __float_as_uint(ab[ks * 8 + 0]);
            const unsigned a2 = __float_as_uint(ab[ks * 8 + 4]);
            const unsigned a1 = __float_as_uint(ab[ks * 8 + 8 * 20]);
            const unsigned a3 = __float_as_uint(ab[ks * 8 + 8 * 20 + 4]);
#pragma unroll
            for (int nt = 0; nt < 16; nt++) {
                const float2 bp = *(const float2*)
                    &Bf[buf][((nt * 8 + g) * 12 + ks * 4 + tig) * 2];
                mma8(d[nt], a0, a1, a2, a3,
                     __float_as_uint(bp.x), __float_as_uint(bp.y));
            }
        }
    };

    const int T = K / 16;
    loadg(0);
    stores(0);
    __syncthreads();
    for (int t = 0; t < T; t++) {
        if (t + 1 < T) loadg((t + 1) * 16);
        compute(t & 1);
        if (t + 1 < T) { stores((t + 1) & 1); __syncthreads(); }
    }

    // ------------------------------ epilogue ------------------------------
    const int colb = 2 * tig;
#pragma unroll
    for (int half = 0; half < 2; half++) {
        const int  row = brow + warp * 16 + g + half * 8;
        const bool ok  = row < M;
        float s = 0.f, ss = 0.f;
#pragma unroll
        for (int nt = 0; nt < 16; nt++) {
            const int col = nt * 8 + colb;
            float x0 = d[nt][half * 2 + 0];
            float x1 = d[nt][half * 2 + 1];
            if (bias) {
                const float2 bi = *(const float2*)&bias[col];
                x0 += bi.x; x1 += bi.y;
            }
            if (resid && ok) {
                const float2 rr = *(const float2*)&resid[(size_t)row * HID + col];
                x0 += rr.x; x1 += rr.y;
            }
            if (relu) { x0 = fmaxf(x0, 0.f); x1 = fmaxf(x1, 0.f); }
            d[nt][half * 2 + 0] = x0;
            d[nt][half * 2 + 1] = x1;
            s  += x0 + x1;
            ss += x0 * x0 + x1 * x1;
        }
        if (do_ln) {
            s  += __shfl_xor_sync(0xffffffffu, s, 1);
            s  += __shfl_xor_sync(0xffffffffu, s, 2);
            ss += __shfl_xor_sync(0xffffffffu, ss, 1);
            ss += __shfl_xor_sync(0xffffffffu, ss, 2);
            const float mean = s * (1.f / 128.f);
            const float inv  = rsqrtf(ss * (1.f / 128.f) - mean * mean + 1e-5f);
#pragma unroll
            for (int nt = 0; nt < 16; nt++) {
                const int col = nt * 8 + colb;
                const float2 gg = *(const float2*)&gamma[col];
                const float2 bb = *(const float2*)&beta[col];
                float2 o;
                o.x = (d[nt][half * 2 + 0] - mean) * inv * gg.x + bb.x;
                o.y = (d[nt][half * 2 + 1] - mean) * inv * gg.y + bb.y;
                if (ok) *(float2*)&C[(size_t)row * HID + col] = o;
            }
        } else if (ok) {
#pragma unroll
            for (int nt = 0; nt < 16; nt++) {
                const int col = nt * 8 + colb;
                *(float2*)&C[(size_t)row * HID + col] =
                    make_float2(d[nt][half * 2 + 0], d[nt][half * 2 + 1]);
            }
        }
    }
}

// ---------------------------------------------------------------------------
// Fused K/V projection: reads h_atom tile ONCE, warps 0-3 compute K, warps
// 4-7 compute V. BM=64, K=N=128. Outputs fp16. Halves HBM traffic vs 2 GEMMs.
// ---------------------------------------------------------------------------
__global__ __launch_bounds__(256) void gemm_kv(
    const float* __restrict__ A,  const float* __restrict__ Bk,
    const float* __restrict__ Bv, __half* __restrict__ Ck,
    __half* __restrict__ Cv, int M)
{
    __shared__ float As[2][64 * 20];
    __shared__ float Bf[2][2][128 * 24];

    const int tid  = threadIdx.x;
    const int warp = tid >> 5;
    const int lane = tid & 31;
    const int g    = lane >> 2;
    const int tig  = lane & 3;
    const int wrow = (warp & 3) * 16;     // warp's row base within block
    const int sel  = warp >> 2;           // 0 = K, 1 = V
    const int brow = blockIdx.x * 64;

    const int ar = tid >> 2, ak = (tid & 3) * 4;  // A: 1 float4/thread
    const int bw = tid >> 7, br = tid & 127;      // B: 4 float4/thread

    float d[16][4];
#pragma unroll
    for (int i = 0; i < 16; i++)
#pragma unroll
        for (int j = 0; j < 4; j++) d[i][j] = 0.f;

    float4 av, bq0, bq1, bq2, bq3;

    auto loadg = [&](int kb) {
        const int r = brow + ar;
        av = (r < M) ? *(const float4*)&A[(size_t)r * HID + kb + ak]
                     : make_float4(0.f, 0.f, 0.f, 0.f);
        const float* Bp = bw ? Bv : Bk;
        bq0 = *(const float4*)&Bp[(size_t)br * HID + kb + 0];
        bq1 = *(const float4*)&Bp[(size_t)br * HID + kb + 4];
        bq2 = *(const float4*)&Bp[(size_t)br * HID + kb + 8];
        bq3 = *(const float4*)&Bp[(size_t)br * HID + kb + 12];
    };

    auto stores = [&](int buf) {
        *(float4*)&As[buf][ar * 20 + ak] = cvt4(av);
        float* bs = &Bf[buf][bw][br * 24];
        *(float4*)&bs[0]  = make_float4(tf32r(bq0.x), tf32r(bq1.x),
                                        tf32r(bq0.y), tf32r(bq1.y));
        *(float4*)&bs[4]  = make_float4(tf32r(bq0.z), tf32r(bq1.z),
                                        tf32r(bq0.w), tf32r(bq1.w));
        *(float4*)&bs[8]  = make_float4(tf32r(bq2.x), tf32r(bq3.x),
                                        tf32r(bq2.y), tf32r(bq3.y));
        *(float4*)&bs[12] = make_float4(tf32r(bq2.z), tf32r(bq3.z),
                                        tf32r(bq2.w), tf32r(bq3.w));
    };

    auto compute = [&](int buf) {
        const float* ab = &As[buf][(wrow + g) * 20 + tig];
        const float* bb = Bf[buf][sel];
#pragma unroll
        for (int ks = 0; ks < 2; ks++) {
            const unsigned a0 = __float_as_uint(ab[ks * 8 + 0]);
            const unsigned a2 = __float_as_uint(ab[ks * 8 + 4]);
            const unsigned a1 = __float_as_uint(ab[ks * 8 + 8 * 20]);
            const unsigned a3 = __float_as_uint(ab[ks * 8 + 8 * 20 + 4]);
#pragma unroll
            for (int nt = 0; nt < 16; nt++) {
                const float2 bp = *(const float2*)
                    &bb[(nt * 8 + g) * 24 + ks * 8 + tig * 2];
                mma8(d[nt], a0, a1, a2, a3,
                     __float_as_uint(bp.x), __float_as_uint(bp.y));
            }
        }
    };

    loadg(0);
    stores(0);
    __syncthreads();
#pragma unroll
    for (int t = 0; t < 8; t++) {
        if (t + 1 < 8) loadg((t + 1) * 16);
        compute(t & 1);
        if (t + 1 < 8) { stores((t + 1) & 1); __syncthreads(); }
    }

    __half* Cp = sel ? Cv : Ck;
#pragma unroll
    for (int half = 0; half < 2; half++) {
        const int row = brow + wrow + g + half * 8;
        if (row >= M) continue;
#pragma unroll
        for (int nt = 0; nt < 16; nt++) {
            const int col = nt * 8 + 2 * tig;
            *(__half2*)&Cp[(size_t)row * HID + col] =
                __floats2half2_rn(d[nt][half * 2 + 0], d[nt][half * 2 + 1]);
        }
    }
}

// ---------------------------------------------------------------------------
// Attention: one warp per query; lane l owns out dims [4l,4l+4) of head l/4.
// K/V gathered as fp16 (half the bytes of round-2).
// ---------------------------------------------------------------------------
__global__ __launch_bounds__(256) void attn_kernel(
    const float* __restrict__ Qq, const __half* __restrict__ Ka,
    const __half* __restrict__ Va, const float* __restrict__ edge_attr,
    const int*   __restrict__ src_idx, const float* __restrict__ W_rbf,
    float* __restrict__ agg)
{
    __shared__ float s_sc[8][8 * 36];
    __shared__ int   s_src[8][32];

    const int warp = threadIdx.x >> 5;
    const int lane = threadIdx.x & 31;
    const int q = blockIdx.x * 8 + warp;
    const int h   = lane >> 2;
    const int sm4 = lane & 3;

    const float4 q4 = *(const float4*)&Qq[(size_t)q * HID + lane * 4];
    const float4 wr = *(const float4*)&W_rbf[h * E_F + sm4 * 4];

    s_src[warp][lane] = src_idx[(size_t)q * KNN + lane];
    __syncwarp();

    // scores
#pragma unroll
    for (int j = 0; j < KNN; j++) {
        const int sj = s_src[warp][j];
        const __half2* kr = (const __half2*)(Ka + (size_t)sj * HID);
        const float2 k01 = __half22float2(kr[lane * 2 + 0]);
        const float2 k23 = __half22float2(kr[lane * 2 + 1]);
        float dd = q4.x * k01.x + q4.y * k01.y + q4.z * k23.x + q4.w * k23.y;
        const float4 e4 = *(const float4*)
            &edge_attr[((size_t)q * KNN + j) * E_F + sm4 * 4];
        const float rr = e4.x * wr.x + e4.y * wr.y + e4.z * wr.z + e4.w * wr.w;
        float t = dd * 0.25f + rr;
        t += __shfl_xor_sync(0xffffffffu, t, 1);
        t += __shfl_xor_sync(0xffffffffu, t, 2);
        if (sm4 == 0) s_sc[warp][h * 36 + j] = t;
    }
    __syncwarp();

    // softmax (lanes split the 32 edges of head h, 8 each)
    float v[8];
    float m = -1e30f;
#pragma unroll
    for (int t = 0; t < 8; t++) {
        v[t] = s_sc[warp][h * 36 + sm4 + 4 * t];
        m = fmaxf(m, v[t]);
    }
    m = fmaxf(m, __shfl_xor_sync(0xffffffffu, m, 1));
    m = fmaxf(m, __shfl_xor_sync(0xffffffffu, m, 2));
    float sum = 0.f;
#pragma unroll
    for (int t = 0; t < 8; t++) { v[t] = __expf(v[t] - m); sum += v[t]; }
    sum += __shfl_xor_sync(0xffffffffu, sum, 1);
    sum += __shfl_xor_sync(0xffffffffu, sum, 2);
    const float inv = 1.f / (sum + 1e-16f);
#pragma unroll
    for (int t = 0; t < 8; t++) s_sc[warp][h * 36 + sm4 + 4 * t] = v[t] * inv;
    __syncwarp();

    // weighted V aggregation
    float4 acc = make_float4(0.f, 0.f, 0.f, 0.f);
#pragma unroll
    for (int j = 0; j < KNN; j++) {
        const float a  = s_sc[warp][h * 36 + j];
        const int   sj = s_src[warp][j];
        const __half2* vr = (const __half2*)(Va + (size_t)sj * HID);
        const float2 v01 = __half22float2(vr[lane * 2 + 0]);
        const float2 v23 = __half22float2(vr[lane * 2 + 1]);
        acc.x = fmaf(a, v01.x, acc.x);
        acc.y = fmaf(a, v01.y, acc.y);
        acc.z = fmaf(a, v23.x, acc.z);
        acc.w = fmaf(a, v23.y, acc.w);
    }
    *(float4*)&agg[(size_t)q * HID + lane * 4] = acc;
}

// ---------------------------------------------------------------------------
extern "C" void kernel_launch(void* const* d_in, const int* in_sizes, int n_in,
                              void* d_out, int out_size)
{
    const float* h_atom    = (const float*)d_in[0];
    const float* h_query   = (const float*)d_in[1];
    const float* edge_attr = (const float*)d_in[2];
    const float* W_q       = (const float*)d_in[3];
    const float* W_k       = (const float*)d_in[4];
    const float* W_v       = (const float*)d_in[5];
    const float* W_rbf     = (const float*)d_in[6];
    const float* W1        = (const float*)d_in[7];
    const float* b1        = (const float*)d_in[8];
    const float* W2        = (const float*)d_in[9];
    const float* b2        = (const float*)d_in[10];
    const float* ln_gamma  = (const float*)d_in[11];
    const float* ln_beta   = (const float*)d_in[12];
    const int*   edge_index= (const int*)  d_in[13];   // [2,E]; row0 = src
    float* out = (float*)d_out;

    float *Qq, *agg, *H1;
    __half *Ka, *Va;
    cudaGetSymbolAddress((void**)&Qq,  g_Qq);
    cudaGetSymbolAddress((void**)&Ka,  g_Ka);
    cudaGetSymbolAddress((void**)&Va,  g_Va);
    cudaGetSymbolAddress((void**)&agg, g_agg);
    cudaGetSymbolAddress((void**)&H1,  g_H1);

    const int gq = (NQ + 127) / 128;   // 157

    // Q projection (fp32 out, tf32 TC)
    gemm_tc<<<gq, 256>>>(h_query, nullptr, W_q, nullptr, nullptr, nullptr, nullptr,
                         Qq, NQ, HID, 0, 0);
    // fused K+V projection (fp16 out) — reads h_atom once
    gemm_kv<<<(NA + 63) / 64, 256>>>(h_atom, W_k, W_v, Ka, Va, NA);

    // segment-softmax attention + aggregation (dst[e] = e / KNN)
    attn_kernel<<<NQ / 8, 256>>>(Qq, Ka, Va, edge_attr, edge_index, W_rbf, agg);

    // MLP1 over concat([h_query, agg]) with ReLU
    gemm_tc<<<gq, 256>>>(h_query, agg, W1, b1, nullptr, nullptr, nullptr,
                         H1, NQ, 2 * HID, 1, 0);
    // MLP2 + bias + residual + LayerNorm fused epilogue
    gemm_tc<<<gq, 256>>>(H1, nullptr, W2, b2, h_query, ln_gamma, ln_beta,
                         out, NQ, HID, 0, 1);
}

// round 4
// speedup vs baseline: 1.7675x; 1.1311x over previous
#include <cuda_runtime.h>
#include <cuda_fp16.h>

#define NQ    20000
#define NA    100000
#define KNN   32
#define HID   128
#define E_F   16
#define HEADS 8

#define KVB   1563              // (NA+63)/64
#define QB    157               // (NQ+127)/128

// ---------------- scratch (static device globals; no runtime alloc) ----------
__device__ __align__(16) float  g_Qq [NQ * HID];
__device__ __align__(16) __half g_Ka [NA * HID];
__device__ __align__(16) __half g_Va [NA * HID];
__device__ __align__(16) float  g_agg[NQ * HID];
__device__ __align__(16) float  g_H1 [NQ * HID];

// ------------------------- tf32 helpers --------------------------------------
__device__ __forceinline__ float tf32r(float x) {
    unsigned u;
    asm("cvt.rna.tf32.f32 %0, %1;" : "=r"(u) : "f"(x));
    return __uint_as_float(u);
}
__device__ __forceinline__ void mma8(float* d, unsigned a0, unsigned a1,
                                     unsigned a2, unsigned a3,
                                     unsigned b0, unsigned b1) {
    asm volatile(
        "mma.sync.aligned.m16n8k8.row.col.f32.tf32.tf32.f32 "
        "{%0,%1,%2,%3}, {%4,%5,%6,%7}, {%8,%9}, {%0,%1,%2,%3};"
        : "+f"(d[0]), "+f"(d[1]), "+f"(d[2]), "+f"(d[3])
        : "r"(a0), "r"(a1), "r"(a2), "r"(a3), "r"(b0), "r"(b1));
}

// B smem pair layout: for row n, Bf[(n*12 + ks*4 + tig)*2 + {0,1}] =
//   { B[n][ks*8+tig], B[n][ks*8+tig+4] }   (24 floats per n)

// ---------------------------------------------------------------------------
// proj_all: 512 threads. blocks [0,KVB): fused K+V projection (BM=64, fp16
// out, warp tile 16x64, 16 warps = {K,V} x 4 rowgroups x 2 colhalves).
// blocks [KVB, KVB+QB): Q projection (BM=128, fp32 out, same warp tiling).
// ---------------------------------------------------------------------------
__global__ __launch_bounds__(512) void proj_all(
    const float* __restrict__ hA, const float* __restrict__ hQ,
    const float* __restrict__ Wk, const float* __restrict__ Wv,
    const float* __restrict__ Wq,
    __half* __restrict__ Ck, __half* __restrict__ Cv, float* __restrict__ Cq)
{
    __shared__ float sm[14848];   // 59392 B, reused by both paths

    const int tid  = threadIdx.x;
    const int warp = tid >> 5;
    const int lane = tid & 31;
    const int g    = lane >> 2;
    const int tig  = lane & 3;

    float d[8][4];
#pragma unroll
    for (int i = 0; i < 8; i++)
#pragma unroll
        for (int j = 0; j < 4; j++) d[i][j] = 0.f;

    if (blockIdx.x < KVB) {
        // ---------------- KV path ----------------
        float* As = sm;              // 2 x 64*20
        float* Bf = sm + 2560;       // 2 x 2 x 128*24
        const int brow = blockIdx.x * 64;
        const int sel  = warp >> 3;          // 0=K, 1=V
        const int mrow = ((warp >> 1) & 3) * 16;
        const int colh = warp & 1;

        const int ar = tid >> 3, ak = (tid & 7) * 2;     // A: float2/thread
        const int bw = tid >> 8;                          // 0 -> Wk, 1 -> Wv
        const int t2 = tid & 255;
        const int br = t2 >> 1, bk = (t2 & 1) * 8;        // B: 2 float4/thread

        float2 av;
        float4 b0, b1;

        auto loadg = [&](int kb) {
            const int r = brow + ar;
            av = (r < NA) ? *(const float2*)&hA[(size_t)r * HID + kb + ak]
                          : make_float2(0.f, 0.f);
            const float* Bp = bw ? Wv : Wk;
            b0 = *(const float4*)&Bp[(size_t)br * HID + kb + bk];
            b1 = *(const float4*)&Bp[(size_t)br * HID + kb + bk + 4];
        };
        auto stores = [&](int buf) {
            float* as = As + buf * 1280 + ar * 20 + ak;
            as[0] = tf32r(av.x); as[1] = tf32r(av.y);
            const int ks = bk >> 3;
            float* bs = Bf + (buf * 2 + bw) * 3072 + (br * 12 + ks * 4) * 2;
            *(float4*)bs       = make_float4(tf32r(b0.x), tf32r(b1.x),
                                             tf32r(b0.y), tf32r(b1.y));
            *(float4*)(bs + 4) = make_float4(tf32r(b0.z), tf32r(b1.z),
                                             tf32r(b0.w), tf32r(b1.w));
        };
        auto compute = [&](int buf) {
            const float* ab = As + buf * 1280 + (mrow + g) * 20 + tig;
            const float* bb = Bf + (buf * 2 + sel) * 3072;
#pragma unroll
            for (int ks = 0; ks < 2; ks++) {
                const unsigned a0 = __float_as_uint(ab[ks * 8 + 0]);
                const unsigned a2 = __float_as_uint(ab[ks * 8 + 4]);
                const unsigned a1 = __float_as_uint(ab[ks * 8 + 160]);
                const unsigned a3 = __float_as_uint(ab[ks * 8 + 164]);
#pragma unroll
                for (int nt = 0; nt < 8; nt++) {
                    const int n = colh * 64 + nt * 8 + g;
                    const float2 bp = *(const float2*)
                        &bb[(n * 12 + ks * 4 + tig) * 2];
                    mma8(d[nt], a0, a1, a2, a3,
                         __float_as_uint(bp.x), __float_as_uint(bp.y));
                }
            }
        };

        loadg(0); stores(0); __syncthreads();
#pragma unroll
        for (int t = 0; t < 8; t++) {
            if (t + 1 < 8) loadg((t + 1) * 16);
            compute(t & 1);
            if (t + 1 < 8) { stores((t + 1) & 1); __syncthreads(); }
        }

        __half* Cp = sel ? Cv : Ck;
#pragma unroll
        for (int half = 0; half < 2; half++) {
            const int row = brow + mrow + g + half * 8;
            if (row >= NA) continue;
#pragma unroll
            for (int nt = 0; nt < 8; nt++) {
                const int col = colh * 64 + nt * 8 + 2 * tig;
                *(__half2*)&Cp[(size_t)row * HID + col] =
                    __floats2half2_rn(d[nt][half * 2 + 0], d[nt][half * 2 + 1]);
            }
        }
    } else {
        // ---------------- Q path ----------------
        float* As = sm;              // 2 x 128*20
        float* Bf = sm + 5120;       // 2 x 128*24
        const int brow = (blockIdx.x - KVB) * 128;
        const int mrow = (warp >> 1) * 16;
        const int colh = warp & 1;

        float4 v0, v1;               // staging (A or B depending on tid)
        const bool isB = tid < 256;
        const int  lr  = (tid & 255) >> 1;
        const int  lc8 = ((tid & 255) & 1) * 8;

        auto loadg = [&](int kb) {
            if (isB) {
                v0 = *(const float4*)&Wq[(size_t)lr * HID + kb + lc8];
                v1 = *(const float4*)&Wq[(size_t)lr * HID + kb + lc8 + 4];
            } else {
                const int r = brow + lr;
                v0 = make_float4(0.f, 0.f, 0.f, 0.f);
                v1 = v0;
                if (r < NQ) {
                    v0 = *(const float4*)&hQ[(size_t)r * HID + kb + lc8];
                    v1 = *(const float4*)&hQ[(size_t)r * HID + kb + lc8 + 4];
                }
            }
        };
        auto stores = [&](int buf) {
            if (isB) {
                const int ks = lc8 >> 3;
                float* bs = Bf + buf * 3072 + (lr * 12 + ks * 4) * 2;
                *(float4*)bs       = make_float4(tf32r(v0.x), tf32r(v1.x),
                                                 tf32r(v0.y), tf32r(v1.y));
                *(float4*)(bs + 4) = make_float4(tf32r(v0.z), tf32r(v1.z),
                                                 tf32r(v0.w), tf32r(v1.w));
            } else {
                float* as = As + buf * 2560 + lr * 20 + lc8;
                as[0] = tf32r(v0.x); as[1] = tf32r(v0.y);
                as[2] = tf32r(v0.z); as[3] = tf32r(v0.w);
                as[4] = tf32r(v1.x); as[5] = tf32r(v1.y);
                as[6] = tf32r(v1.z); as[7] = tf32r(v1.w);
            }
        };
        auto compute = [&](int buf) {
            const float* ab = As + buf * 2560 + (mrow + g) * 20 + tig;
            const float* bb = Bf + buf * 3072;
#pragma unroll
            for (int ks = 0; ks < 2; ks++) {
                const unsigned a0 = __float_as_uint(ab[ks * 8 + 0]);
                const unsigned a2 = __float_as_uint(ab[ks * 8 + 4]);
                const unsigned a1 = __float_as_uint(ab[ks * 8 + 160]);
                const unsigned a3 = __float_as_uint(ab[ks * 8 + 164]);
#pragma unroll
                for (int nt = 0; nt < 8; nt++) {
                    const int n = colh * 64 + nt * 8 + g;
                    const float2 bp = *(const float2*)
                        &bb[(n * 12 + ks * 4 + tig) * 2];
                    mma8(d[nt], a0, a1, a2, a3,
                         __float_as_uint(bp.x), __float_as_uint(bp.y));
                }
            }
        };

        loadg(0); stores(0); __syncthreads();
#pragma unroll
        for (int t = 0; t < 8; t++) {
            if (t + 1 < 8) loadg((t + 1) * 16);
            compute(t & 1);
            if (t + 1 < 8) { stores((t + 1) & 1); __syncthreads(); }
        }

#pragma unroll
        for (int half = 0; half < 2; half++) {
            const int row = brow + mrow + g + half * 8;
            if (row >= NQ) continue;
#pragma unroll
            for (int nt = 0; nt < 8; nt++) {
                const int col = colh * 64 + nt * 8 + 2 * tig;
                *(float2*)&Cq[(size_t)row * HID + col] =
                    make_float2(d[nt][half * 2 + 0], d[nt][half * 2 + 1]);
            }
        }
    }
}

// ---------------------------------------------------------------------------
// gemm64: C[M,128] = f(A @ B^T + bias [+resid]) (ReLU / LayerNorm). BM=64,
// 256 threads, warp tile 16x64 (32 accs) -> 2 CTAs/SM. A = concat(A0,A1)
// along K when A1 != null (K=256). LN row-sums combined across the 2
// col-half warps via smem.
// ---------------------------------------------------------------------------
__global__ __launch_bounds__(256, 2) void gemm64(
    const float* __restrict__ A0, const float* __restrict__ A1,
    const float* __restrict__ B,  const float* __restrict__ bias,
    const float* __restrict__ resid, const float* __restrict__ gamma,
    const float* __restrict__ beta, float* __restrict__ C,
    int M, int K, int relu, int do_ln)
{
    __shared__ float As[2][64 * 20];
    __shared__ float Bf[2][128 * 24];

    const int tid  = threadIdx.x;
    const int warp = tid >> 5;
    const int lane = tid & 31;
    const int g    = lane >> 2;
    const int tig  = lane & 3;
    const int mrow = (warp >> 1) * 16;
    const int colh = warp & 1;
    const int brow = blockIdx.x * 64;

    const int ar = tid >> 2, ak = (tid & 3) * 4;   // A: 1 float4/thread
    const int lr = tid >> 1, lc = (tid & 1) * 8;   // B: 2 float4/thread

    float d[8][4];
#pragma unroll
    for (int i = 0; i < 8; i++)
#pragma unroll
        for (int j = 0; j < 4; j++) d[i][j] = 0.f;

    float4 av, b0, b1;

    auto loadg = [&](int kb) {
        const float* Ap = (A1 != nullptr && kb >= HID) ? A1 : A0;
        const int    ko = (A1 != nullptr && kb >= HID) ? (kb - HID) : kb;
        const int r = brow + ar;
        av = (r < M) ? *(const float4*)&Ap[(size_t)r * HID + ko + ak]
                     : make_float4(0.f, 0.f, 0.f, 0.f);
        b0 = *(const float4*)&B[(size_t)lr * K + kb + lc];
        b1 = *(const float4*)&B[(size_t)lr * K + kb + lc + 4];
    };
    auto stores = [&](int buf) {
        float* as = &As[buf][ar * 20 + ak];
        as[0] = tf32r(av.x); as[1] = tf32r(av.y);
        as[2] = tf32r(av.z); as[3] = tf32r(av.w);
        const int ks = lc >> 3;
        float* bs = &Bf[buf][(lr * 12 + ks * 4) * 2];
        *(float4*)bs       = make_float4(tf32r(b0.x), tf32r(b1.x),
                                         tf32r(b0.y), tf32r(b1.y));
        *(float4*)(bs + 4) = make_float4(tf32r(b0.z), tf32r(b1.z),
                                         tf32r(b0.w), tf32r(b1.w));
    };
    auto compute = [&](int buf) {
        const float* ab = &As[buf][(mrow + g) * 20 + tig];
#pragma unroll
        for (int ks = 0; ks < 2; ks++) {
            const unsigned a0 = __float_as_uint(ab[ks * 8 + 0]);
            const unsigned a2 = __float_as_uint(ab[ks * 8 + 4]);
            const unsigned a1 = __float_as_uint(ab[ks * 8 + 160]);
            const unsigned a3 = __float_as_uint(ab[ks * 8 + 164]);
#pragma unroll
            for (int nt = 0; nt < 8; nt++) {
                const int n = colh * 64 + nt * 8 + g;
                const float2 bp = *(const float2*)
                    &Bf[buf][(n * 12 + ks * 4 + tig) * 2];
                mma8(d[nt], a0, a1, a2, a3,
                     __float_as_uint(bp.x), __float_as_uint(bp.y));
            }
        }
    };

    const int T = K / 16;
    loadg(0); stores(0); __syncthreads();
    for (int t = 0; t < T; t++) {
        if (t + 1 < T) loadg((t + 1) * 16);
        compute(t & 1);
        if (t + 1 < T) { stores((t + 1) & 1); __syncthreads(); }
    }

    // ------------------------------ epilogue ------------------------------
    // pass 1: bias/resid/relu + per-(row,colhalf) partial sums
    float psum[2], psq[2];
#pragma unroll
    for (int half = 0; half < 2; half++) {
        const int  row = brow + mrow + g + half * 8;
        const bool ok  = row < M;
        float s = 0.f, ss = 0.f;
#pragma unroll
        for (int nt = 0; nt < 8; nt++) {
            const int col = colh * 64 + nt * 8 + 2 * tig;
            float x0 = d[nt][half * 2 + 0];
            float x1 = d[nt][half * 2 + 1];
            if (bias) {
                const float2 bi = *(const float2*)&bias[col];
                x0 += bi.x; x1 += bi.y;
            }
            if (resid && ok) {
                const float2 rr = *(const float2*)&resid[(size_t)row * HID + col];
                x0 += rr.x; x1 += rr.y;
            }
            if (relu) { x0 = fmaxf(x0, 0.f); x1 = fmaxf(x1, 0.f); }
            d[nt][half * 2 + 0] = x0;
            d[nt][half * 2 + 1] = x1;
            s  += x0 + x1;
            ss += x0 * x0 + x1 * x1;
        }
        s  += __shfl_xor_sync(0xffffffffu, s, 1);
        s  += __shfl_xor_sync(0xffffffffu, s, 2);
        ss += __shfl_xor_sync(0xffffffffu, ss, 1);
        ss += __shfl_xor_sync(0xffffffffu, ss, 2);
        psum[half] = s; psq[half] = ss;
    }

    if (do_ln) {
        float2* scr = (float2*)&As[0][0];   // 64 rows x 2 colhalves
        __syncthreads();                    // all MMA smem reads done
#pragma unroll
        for (int half = 0; half < 2; half++) {
            const int rl = mrow + g + half * 8;
            if (tig == 0) scr[rl * 2 + colh] = make_float2(psum[half], psq[half]);
        }
        __syncthreads();
#pragma unroll
        for (int half = 0; half < 2; half++) {
            const int rl  = mrow + g + half * 8;
            const int row = brow + rl;
            const float2 f0 = scr[rl * 2 + 0];
            const float2 f1 = scr[rl * 2 + 1];
            const float mean = (f0.x + f1.x) * (1.f / 128.f);
            const float inv  = rsqrtf((f0.y + f1.y) * (1.f / 128.f)
                                      - mean * mean + 1e-5f);
            if (row >= M) continue;
#pragma unroll
            for (int nt = 0; nt < 8; nt++) {
                const int col = colh * 64 + nt * 8 + 2 * tig;
                const float2 gg = *(const float2*)&gamma[col];
                const float2 bb = *(const float2*)&beta[col];
                float2 o;
                o.x = (d[nt][half * 2 + 0] - mean) * inv * gg.x + bb.x;
                o.y = (d[nt][half * 2 + 1] - mean) * inv * gg.y + bb.y;
                *(float2*)&C[(size_t)row * HID + col] = o;
            }
        }
    } else {
#pragma unroll
        for (int half = 0; half < 2; half++) {
            const int row = brow + mrow + g + half * 8;
            if (row >= M) continue;
#pragma unroll
            for (int nt = 0; nt < 8; nt++) {
                const int col = colh * 64 + nt * 8 + 2 * tig;
                *(float2*)&C[(size_t)row * HID + col] =
                    make_float2(d[nt][half * 2 + 0], d[nt][half * 2 + 1]);
            }
        }
    }
}

// ---------------------------------------------------------------------------
// Attention: one warp per query; lane l owns out dims [4l,4l+4) of head l/4.
// ---------------------------------------------------------------------------
__global__ __launch_bounds__(256) void attn_kernel(
    const float* __restrict__ Qq, const __half* __restrict__ Ka,
    const __half* __restrict__ Va, const float* __restrict__ edge_attr,
    const int*   __restrict__ src_idx, const float* __restrict__ W_rbf,
    float* __restrict__ agg)
{
    __shared__ float s_sc[8][8 * 36];
    __shared__ int   s_src[8][32];

    const int warp = threadIdx.x >> 5;
    const int lane = threadIdx.x & 31;
    const int q = blockIdx.x * 8 + warp;
    const int h   = lane >> 2;
    const int sm4 = lane & 3;

    const float4 q4 = *(const float4*)&Qq[(size_t)q * HID + lane * 4];
    const float4 wr = *(const float4*)&W_rbf[h * E_F + sm4 * 4];

    s_src[warp][lane] = src_idx[(size_t)q * KNN + lane];
    __syncwarp();

#pragma unroll
    for (int j = 0; j < KNN; j++) {
        const int sj = s_src[warp][j];
        const __half2* kr = (const __half2*)(Ka + (size_t)sj * HID);
        const float2 k01 = __half22float2(kr[lane * 2 + 0]);
        const float2 k23 = __half22float2(kr[lane * 2 + 1]);
        float dd = q4.x * k01.x + q4.y * k01.y + q4.z * k23.x + q4.w * k23.y;
        const float4 e4 = *(const float4*)
            &edge_attr[((size_t)q * KNN + j) * E_F + sm4 * 4];
        const float rr = e4.x * wr.x + e4.y * wr.y + e4.z * wr.z + e4.w * wr.w;
        float t = dd * 0.25f + rr;
        t += __shfl_xor_sync(0xffffffffu, t, 1);
        t += __shfl_xor_sync(0xffffffffu, t, 2);
        if (sm4 == 0) s_sc[warp][h * 36 + j] = t;
    }
    __syncwarp();

    float v[8];
    float m = -1e30f;
#pragma unroll
    for (int t = 0; t < 8; t++) {
        v[t] = s_sc[warp][h * 36 + sm4 + 4 * t];
        m = fmaxf(m, v[t]);
    }
    m = fmaxf(m, __shfl_xor_sync(0xffffffffu, m, 1));
    m = fmaxf(m, __shfl_xor_sync(0xffffffffu, m, 2));
    float sum = 0.f;
#pragma unroll
    for (int t = 0; t < 8; t++) { v[t] = __expf(v[t] - m); sum += v[t]; }
    sum += __shfl_xor_sync(0xffffffffu, sum, 1);
    sum += __shfl_xor_sync(0xffffffffu, sum, 2);
    const float inv = 1.f / (sum + 1e-16f);
#pragma unroll
    for (int t = 0; t < 8; t++) s_sc[warp][h * 36 + sm4 + 4 * t] = v[t] * inv;
    __syncwarp();

    float4 acc = make_float4(0.f, 0.f, 0.f, 0.f);
#pragma unroll
    for (int j = 0; j < KNN; j++) {
        const float a  = s_sc[warp][h * 36 + j];
        const int   sj = s_src[warp][j];
        const __half2* vr = (const __half2*)(Va + (size_t)sj * HID);
        const float2 v01 = __half22float2(vr[lane * 2 + 0]);
        const float2 v23 = __half22float2(vr[lane * 2 + 1]);
        acc.x = fmaf(a, v01.x, acc.x);
        acc.y = fmaf(a, v01.y, acc.y);
        acc.z = fmaf(a, v23.x, acc.z);
        acc.w = fmaf(a, v23.y, acc.w);
    }
    *(float4*)&agg[(size_t)q * HID + lane * 4] = acc;
}

// ---------------------------------------------------------------------------
extern "C" void kernel_launch(void* const* d_in, const int* in_sizes, int n_in,
                              void* d_out, int out_size)
{
    const float* h_atom    = (const float*)d_in[0];
    const float* h_query   = (const float*)d_in[1];
    const float* edge_attr = (const float*)d_in[2];
    const float* W_q       = (const float*)d_in[3];
    const float* W_k       = (const float*)d_in[4];
    const float* W_v       = (const float*)d_in[5];
    const float* W_rbf     = (const float*)d_in[6];
    const float* W1        = (const float*)d_in[7];
    const float* b1        = (const float*)d_in[8];
    const float* W2        = (const float*)d_in[9];
    const float* b2        = (const float*)d_in[10];
    const float* ln_gamma  = (const float*)d_in[11];
    const float* ln_beta   = (const float*)d_in[12];
    const int*   edge_index= (const int*)  d_in[13];   // [2,E]; row0 = src
    float* out = (float*)d_out;

    float *Qq, *agg, *H1;
    __half *Ka, *Va;
    cudaGetSymbolAddress((void**)&Qq,  g_Qq);
    cudaGetSymbolAddress((void**)&Ka,  g_Ka);
    cudaGetSymbolAddress((void**)&Va,  g_Va);
    cudaGetSymbolAddress((void**)&agg, g_agg);
    cudaGetSymbolAddress((void**)&H1,  g_H1);

    // Q + K + V projections in ONE launch (Q blocks hide under KV memory time)
    proj_all<<<KVB + QB, 512>>>(h_atom, h_query, W_k, W_v, W_q, Ka, Va, Qq);

    // segment-softmax attention + aggregation (dst[e] = e / KNN)
    attn_kernel<<<NQ / 8, 256>>>(Qq, Ka, Va, edge_attr, edge_index, W_rbf, agg);

    // MLP1 over concat([h_query, agg]) with ReLU
    gemm64<<<(NQ + 63) / 64, 256>>>(h_query, agg, W1, b1, nullptr, nullptr,
                                    nullptr, H1, NQ, 2 * HID, 1, 0);
    // MLP2 + bias + residual + LayerNorm fused epilogue
    gemm64<<<(NQ + 63) / 64, 256>>>(H1, nullptr, W2, b2, h_query, ln_gamma,
                                    ln_beta, out, NQ, HID, 0, 1);
}

// round 6
// speedup vs baseline: 2.1662x; 1.2255x over previous
#include <cuda_runtime.h>
#include <cuda_fp16.h>

#define NQ    20000
#define NA    100000
#define KNN   32
#define HID   128
#define E_F   16

#define KVB   1563              // (NA+63)/64
#define QB    157               // (NQ+127)/128
#define MLPB  157               // (NQ+127)/128

// ---------------- scratch (static device globals; no runtime alloc) ----------
__device__ __align__(16) float  g_Qq [NQ * HID];
__device__ __align__(16) __half g_Ka [NA * HID];
__device__ __align__(16) __half g_Va [NA * HID];
__device__ __align__(16) float  g_agg[NQ * HID];

// ------------------------- fp16 MMA helpers ----------------------------------
__device__ __forceinline__ unsigned ph2(float x, float y) {
    __half2 h = __floats2half2_rn(x, y);
    return *reinterpret_cast<unsigned*>(&h);
}
__device__ __forceinline__ void mma16(float* d, unsigned a0, unsigned a1,
                                      unsigned a2, unsigned a3,
                                      unsigned b0, unsigned b1) {
    asm volatile(
        "mma.sync.aligned.m16n8k16.row.col.f32.f16.f16.f32 "
        "{%0,%1,%2,%3}, {%4,%5,%6,%7}, {%8,%9}, {%0,%1,%2,%3};"
        : "+f"(d[0]), "+f"(d[1]), "+f"(d[2]), "+f"(d[3])
        : "r"(a0), "r"(a1), "r"(a2), "r"(a3), "r"(b0), "r"(b1));
}

// Fragment storage (uint2 per (chunk,row,tig)): idx = (chunk*ROWS + row)*4 + tig
//   .x = half2{ M[row][16c+2tig],   M[row][16c+2tig+1] }
//   .y = half2{ M[row][16c+2tig+8], M[row][16c+2tig+9] }
// Chunk-major => row stride 32B => conflict-free 64b LDS per half-warp phase.

// Load weight matrix W [128 rows][K cols] fp32 -> frags at U (uint view).
// lgkf4 = log2(K/4). 512 threads.
__device__ __forceinline__ void load_w_frags(const float* __restrict__ W,
                                             unsigned* U, int lgkf4, int tid) {
    const int nf4 = 128 << lgkf4;
    for (int idx = tid; idx < nf4; idx += 512) {
        const int row = idx >> lgkf4;
        const int c4  = idx & ((1 << lgkf4) - 1);
        const float4 f = ((const float4*)W)[idx];
        const int chunk = c4 >> 2;
        const int j0 = (c4 & 3) * 2;          // 0,2,4,6
        const int j1 = j0 | 1;
        const unsigned base = ((chunk * 128 + row) * 4) * 2;
        U[base + ((j0 & 3) << 1) + (j0 >> 2)] = ph2(f.x, f.y);
        U[base + ((j1 & 3) << 1) + (j1 >> 2)] = ph2(f.z, f.w);
    }
}

// Load activation block A (fp32, row stride 128): AR rows -> frags (8 chunks).
__device__ __forceinline__ void load_a_frags(const float* __restrict__ A,
                                             unsigned* U, int rowbase, int AR,
                                             int maxrow, int tid) {
    const int nf4 = AR * 32;
    for (int idx = tid; idx < nf4; idx += 512) {
        const int row = idx >> 5;
        const int c4  = idx & 31;
        const int gr  = rowbase + row;
        float4 f = make_float4(0.f, 0.f, 0.f, 0.f);
        if (gr < maxrow) f = ((const float4*)A)[(size_t)gr * 32 + c4];
        const int chunk = c4 >> 2;
        const int j0 = (c4 & 3) * 2;
        const int j1 = j0 | 1;
        const unsigned base = ((chunk * AR + row) * 4) * 2;
        U[base + ((j0 & 3) << 1) + (j0 >> 2)] = ph2(f.x, f.y);
        U[base + ((j1 & 3) << 1) + (j1 >> 2)] = ph2(f.z, f.w);
    }
}

// Warp-tile 16x64 GEMM over 8 k16 chunks: d += A(16 rows) @ W^T(64 cols).
__device__ __forceinline__ void gemm_frag(const uint2* __restrict__ AF, int AR,
                                          const uint2* __restrict__ WF, int wcoff,
                                          float d[8][4], int mrow, int colh,
                                          int g, int tig) {
#pragma unroll
    for (int c = 0; c < 8; c++) {
        const uint2 aA = AF[(c * AR + mrow + g) * 4 + tig];
        const uint2 aB = AF[(c * AR + mrow + 8 + g) * 4 + tig];
#pragma unroll
        for (int nt = 0; nt < 8; nt++) {
            const int n = colh * 64 + nt * 8 + g;
            const uint2 b = WF[((wcoff + c) * 128 + n) * 4 + tig];
            mma16(d[nt], aA.x, aB.x, aA.y, aB.y, b.x, b.y);
        }
    }
}

// ---------------------------------------------------------------------------
// proj_all: blocks [0,KVB): K+V projection, BM=64, fp16 out. 16 warps =
// {K,V} x 4 rowgroups x 2 colhalves. Weights Wk,Wv smem-resident as frags.
// blocks [KVB,KVB+QB): Q projection, BM=128, fp32 out, Wq resident.
// Dyn smem 80KB: [Wk 32K][Wv 32K][A 16K]  /  Q: [Wq 32K][A 32K].
// ---------------------------------------------------------------------------
__global__ __launch_bounds__(512, 2) void proj_all(
    const float* __restrict__ hA, const float* __restrict__ hQ,
    const float* __restrict__ Wk, const float* __restrict__ Wv,
    const float* __restrict__ Wq,
    __half* __restrict__ Ck, __half* __restrict__ Cv, float* __restrict__ Cq)
{
    extern __shared__ unsigned U[];
    const int tid  = threadIdx.x;
    const int warp = tid >> 5;
    const int lane = tid & 31;
    const int g    = lane >> 2;
    const int tig  = lane & 3;

    float d[8][4];
#pragma unroll
    for (int i = 0; i < 8; i++)
#pragma unroll
        for (int j = 0; j < 4; j++) d[i][j] = 0.f;

    if (blockIdx.x < KVB) {
        const int brow = blockIdx.x * 64;
        load_w_frags(Wk, U,         5, tid);
        load_w_frags(Wv, U + 8192,  5, tid);
        load_a_frags(hA, U + 16384, brow, 64, NA, tid);
        __syncthreads();

        const int sel  = warp >> 3;
        const int mrow = ((warp >> 1) & 3) * 16;
        const int colh = warp & 1;
        gemm_frag((const uint2*)(U + 16384), 64,
                  (const uint2*)(U + sel * 8192), 0, d, mrow, colh, g, tig);

        __half* Cp = sel ? Cv : Ck;
#pragma unroll
        for (int half = 0; half < 2; half++) {
            const int row = brow + mrow + g + half * 8;
            if (row >= NA) continue;
#pragma unroll
            for (int nt = 0; nt < 8; nt++) {
                const int col = colh * 64 + nt * 8 + 2 * tig;
                *(unsigned*)&Cp[(size_t)row * HID + col] =
                    ph2(d[nt][half * 2 + 0], d[nt][half * 2 + 1]);
            }
        }
    } else {
        const int brow = (blockIdx.x - KVB) * 128;
        load_w_frags(Wq, U, 5, tid);
        load_a_frags(hQ, U + 8192, brow, 128, NQ, tid);
        __syncthreads();

        const int mrow = (warp >> 1) * 16;
        const int colh = warp & 1;
        gemm_frag((const uint2*)(U + 8192), 128,
                  (const uint2*)U, 0, d, mrow, colh, g, tig);

#pragma unroll
        for (int half = 0; half < 2; half++) {
            const int row = brow + mrow + g + half * 8;
            if (row >= NQ) continue;
#pragma unroll
            for (int nt = 0; nt < 8; nt++) {
                const int col = colh * 64 + nt * 8 + 2 * tig;
                *(float2*)&Cq[(size_t)row * HID + col] =
                    make_float2(d[nt][half * 2 + 0], d[nt][half * 2 + 1]);
            }
        }
    }
}

// ---------------------------------------------------------------------------
// mlp_fused: per block of 128 query rows:
//   H1 = relu(concat(h_query, agg) @ W1^T + b1)   (K=256, two A phases)
//   out = LN(h_query + H1 @ W2^T + b2) * gamma + beta
// Dyn smem 96KB: [W1 64K (later W2 32K)][A/H1 frags 32K]. LN scratch static.
// ---------------------------------------------------------------------------
__global__ __launch_bounds__(512, 2) void mlp_fused(
    const float* __restrict__ hQ, const float* __restrict__ agg,
    const float* __restrict__ W1, const float* __restrict__ b1,
    const float* __restrict__ W2, const float* __restrict__ b2,
    const float* __restrict__ gamma, const float* __restrict__ beta,
    float* __restrict__ out)
{
    extern __shared__ unsigned U[];
    __shared__ float2 scr[256];             // [128 rows][2 colhalves] (static)
    unsigned* AU = U + 16384;

    const int tid  = threadIdx.x;
    const int warp = tid >> 5;
    const int lane = tid & 31;
    const int g    = lane >> 2;
    const int tig  = lane & 3;
    const int mrow = (warp >> 1) * 16;
    const int colh = warp & 1;
    const int brow = blockIdx.x * 128;

    float d[8][4];
#pragma unroll
    for (int i = 0; i < 8; i++)
#pragma unroll
        for (int j = 0; j < 4; j++) d[i][j] = 0.f;

    // ---- MLP1: K=256 over [h_query | agg] ----
    load_w_frags(W1, U, 6, tid);                 // 16 chunks resident
    load_a_frags(hQ, AU, brow, 128, NQ, tid);
    __syncthreads();
    gemm_frag((const uint2*)AU, 128, (const uint2*)U, 0, d, mrow, colh, g, tig);
    __syncthreads();
    load_a_frags(agg, AU, brow, 128, NQ, tid);
    __syncthreads();
    gemm_frag((const uint2*)AU, 128, (const uint2*)U, 8, d, mrow, colh, g, tig);
    __syncthreads();

    // ---- bias + ReLU; repack H1 tile as A-fragments; load W2 ----
#pragma unroll
    for (int half = 0; half < 2; half++) {
        const int rl = mrow + g + half * 8;
#pragma unroll
        for (int nt = 0; nt < 8; nt++) {
            const int col = colh * 64 + nt * 8 + 2 * tig;
            const float2 bi = *(const float2*)&b1[col];
            const float x0 = fmaxf(d[nt][half * 2 + 0] + bi.x, 0.f);
            const float x1 = fmaxf(d[nt][half * 2 + 1] + bi.y, 0.f);
            const int chunk = colh * 4 + (nt >> 1);
            AU[((chunk * 128 + rl) * 4 + tig) * 2 + (nt & 1)] = ph2(x0, x1);
        }
    }
    load_w_frags(W2, U, 5, tid);
    __syncthreads();

    // ---- MLP2 ----
#pragma unroll
    for (int i = 0; i < 8; i++)
#pragma unroll
        for (int j = 0; j < 4; j++) d[i][j] = 0.f;
    gemm_frag((const uint2*)AU, 128, (const uint2*)U, 0, d, mrow, colh, g, tig);

    // ---- b2 + residual + LayerNorm ----
    float psum[2], psq[2];
#pragma unroll
    for (int half = 0; half < 2; half++) {
        const int  row = brow + mrow + g + half * 8;
        const bool ok  = row < NQ;
        float s = 0.f, ss = 0.f;
#pragma unroll
        for (int nt = 0; nt < 8; nt++) {
            const int col = colh * 64 + nt * 8 + 2 * tig;
            const float2 bi = *(const float2*)&b2[col];
            float x0 = d[nt][half * 2 + 0] + bi.x;
            float x1 = d[nt][half * 2 + 1] + bi.y;
            if (ok) {
                const float2 rr = *(const float2*)&hQ[(size_t)row * HID + col];
                x0 += rr.x; x1 += rr.y;
            }
            d[nt][half * 2 + 0] = x0;
            d[nt][half * 2 + 1] = x1;
            s  += x0 + x1;
            ss += x0 * x0 + x1 * x1;
        }
        s  += __shfl_xor_sync(0xffffffffu, s, 1);
        s  += __shfl_xor_sync(0xffffffffu, s, 2);
        ss += __shfl_xor_sync(0xffffffffu, ss, 1);
        ss += __shfl_xor_sync(0xffffffffu, ss, 2);
        psum[half] = s; psq[half] = ss;
    }
#pragma unroll
    for (int half = 0; half < 2; half++) {
        const int rl = mrow + g + half * 8;
        if (tig == 0) scr[rl * 2 + colh] = make_float2(psum[half], psq[half]);
    }
    __syncthreads();
#pragma unroll
    for (int half = 0; half < 2; half++) {
        const int rl  = mrow + g + half * 8;
        const int row = brow + rl;
        const float2 f0 = scr[rl * 2 + 0];
        const float2 f1 = scr[rl * 2 + 1];
        const float mean = (f0.x + f1.x) * (1.f / 128.f);
        const float inv  = rsqrtf((f0.y + f1.y) * (1.f / 128.f)
                                  - mean * mean + 1e-5f);
        if (row >= NQ) continue;
#pragma unroll
        for (int nt = 0; nt < 8; nt++) {
            const int col = colh * 64 + nt * 8 + 2 * tig;
            const float2 gg = *(const float2*)&gamma[col];
            const float2 bb = *(const float2*)&beta[col];
            float2 o;
            o.x = (d[nt][half * 2 + 0] - mean) * inv * gg.x + bb.x;
            o.y = (d[nt][half * 2 + 1] - mean) * inv * gg.y + bb.y;
            *(float2*)&out[(size_t)row * HID + col] = o;
        }
    }
}

// ---------------------------------------------------------------------------
// Attention: one warp per query; lane l owns out dims [4l,4l+4) of head l/4.
// ---------------------------------------------------------------------------
__global__ __launch_bounds__(256) void attn_kernel(
    const float* __restrict__ Qq, const __half* __restrict__ Ka,
    const __half* __restrict__ Va, const float* __restrict__ edge_attr,
    const int*   __restrict__ src_idx, const float* __restrict__ W_rbf,
    float* __restrict__ agg)
{
    __shared__ float s_sc[8][8 * 36];
    __shared__ int   s_src[8][32];

    const int warp = threadIdx.x >> 5;
    const int lane = threadIdx.x & 31;
    const int q = blockIdx.x * 8 + warp;
    const int h   = lane >> 2;
    const int sm4 = lane & 3;

    const float4 q4 = *(const float4*)&Qq[(size_t)q * HID + lane * 4];
    const float4 wr = *(const float4*)&W_rbf[h * E_F + sm4 * 4];

    s_src[warp][lane] = src_idx[(size_t)q * KNN + lane];
    __syncwarp();

#pragma unroll
    for (int j = 0; j < KNN; j++) {
        const int sj = s_src[warp][j];
        const __half2* kr = (const __half2*)(Ka + (size_t)sj * HID);
        const float2 k01 = __half22float2(kr[lane * 2 + 0]);
        const float2 k23 = __half22float2(kr[lane * 2 + 1]);
        float dd = q4.x * k01.x + q4.y * k01.y + q4.z * k23.x + q4.w * k23.y;
        const float4 e4 = *(const float4*)
            &edge_attr[((size_t)q * KNN + j) * E_F + sm4 * 4];
        const float rr = e4.x * wr.x + e4.y * wr.y + e4.z * wr.z + e4.w * wr.w;
        float t = dd * 0.25f + rr;
        t += __shfl_xor_sync(0xffffffffu, t, 1);
        t += __shfl_xor_sync(0xffffffffu, t, 2);
        if (sm4 == 0) s_sc[warp][h * 36 + j] = t;
    }
    __syncwarp();

    float v[8];
    float m = -1e30f;
#pragma unroll
    for (int t = 0; t < 8; t++) {
        v[t] = s_sc[warp][h * 36 + sm4 + 4 * t];
        m = fmaxf(m, v[t]);
    }
    m = fmaxf(m, __shfl_xor_sync(0xffffffffu, m, 1));
    m = fmaxf(m, __shfl_xor_sync(0xffffffffu, m, 2));
    float sum = 0.f;
#pragma unroll
    for (int t = 0; t < 8; t++) { v[t] = __expf(v[t] - m); sum += v[t]; }
    sum += __shfl_xor_sync(0xffffffffu, sum, 1);
    sum += __shfl_xor_sync(0xffffffffu, sum, 2);
    const float inv = 1.f / (sum + 1e-16f);
#pragma unroll
    for (int t = 0; t < 8; t++) s_sc[warp][h * 36 + sm4 + 4 * t] = v[t] * inv;
    __syncwarp();

    float4 acc = make_float4(0.f, 0.f, 0.f, 0.f);
#pragma unroll
    for (int j = 0; j < KNN; j++) {
        const float a  = s_sc[warp][h * 36 + j];
        const int   sj = s_src[warp][j];
        const __half2* vr = (const __half2*)(Va + (size_t)sj * HID);
        const float2 v01 = __half22float2(vr[lane * 2 + 0]);
        const float2 v23 = __half22float2(vr[lane * 2 + 1]);
        acc.x = fmaf(a, v01.x, acc.x);
        acc.y = fmaf(a, v01.y, acc.y);
        acc.z = fmaf(a, v23.x, acc.z);
        acc.w = fmaf(a, v23.y, acc.w);
    }
    *(float4*)&agg[(size_t)q * HID + lane * 4] = acc;
}

// ---------------------------------------------------------------------------
extern "C" void kernel_launch(void* const* d_in, const int* in_sizes, int n_in,
                              void* d_out, int out_size)
{
    const float* h_atom    = (const float*)d_in[0];
    const float* h_query   = (const float*)d_in[1];
    const float* edge_attr = (const float*)d_in[2];
    const float* W_q       = (const float*)d_in[3];
    const float* W_k       = (const float*)d_in[4];
    const float* W_v       = (const float*)d_in[5];
    const float* W_rbf     = (const float*)d_in[6];
    const float* W1        = (const float*)d_in[7];
    const float* b1        = (const float*)d_in[8];
    const float* W2        = (const float*)d_in[9];
    const float* b2        = (const float*)d_in[10];
    const float* ln_gamma  = (const float*)d_in[11];
    const float* ln_beta   = (const float*)d_in[12];
    const int*   edge_index= (const int*)  d_in[13];   // [2,E]; row0 = src
    float* out = (float*)d_out;

    float *Qq, *agg;
    __half *Ka, *Va;
    cudaGetSymbolAddress((void**)&Qq,  g_Qq);
    cudaGetSymbolAddress((void**)&Ka,  g_Ka);
    cudaGetSymbolAddress((void**)&Va,  g_Va);
    cudaGetSymbolAddress((void**)&agg, g_agg);

    cudaFuncSetAttribute(proj_all,
                         cudaFuncAttributeMaxDynamicSharedMemorySize, 81920);
    cudaFuncSetAttribute(mlp_fused,
                         cudaFuncAttributeMaxDynamicSharedMemorySize, 98304);

    // Q + K + V projections in one launch (fp16 MMA, weights smem-resident)
    proj_all<<<KVB + QB, 512, 81920>>>(h_atom, h_query, W_k, W_v, W_q,
                                       Ka, Va, Qq);

    // segment-softmax attention + aggregation (dst[e] = e / KNN)
    attn_kernel<<<NQ / 8, 256>>>(Qq, Ka, Va, edge_attr, edge_index, W_rbf, agg);

    // fused MLP1 + ReLU + MLP2 + residual + LayerNorm
    mlp_fused<<<MLPB, 512, 98304>>>(h_query, agg, W1, b1, W2, b2,
                                    ln_gamma, ln_beta, out);
}